// round 15
// baseline (speedup 1.0000x reference)
#include <cuda_runtime.h>
#include <cuda_bf16.h>

// Haar wavelet 2x2 transform — FINAL champion (512-thread CTAs).
// Input:  x[B=8, C=64, H=512, W=512] fp32
// Output: out[B=8, 4*C=256, H/2=256, W/2=256] fp32
// out channel = 4*c + band, band in {ll, lh, hl, hh}.
//
// One thread = 2 output columns (1 float2 per plane):
//   loads  : LDG.128 lane-dense (512 B contiguous per warp per instruction)
//   stores : STG.64 lane-dense (256 B contiguous per warp per instruction)
// Every memory instruction touches each 128B line exactly once.
// 14-round sweep (MLP, lane density, cache policy, persistence, CTA size)
// converged all well-formed variants to ~6.8 TB/s (85-87% of 8 TB/s spec) —
// the 1:1 read/write mixed-stream HBM ceiling. Traffic is minimal (1 GiB).

#define B_ 8
#define C_ 64
#define H_ 512
#define W_ 512
#define H2_ (H_ / 2)
#define W2_ (W_ / 2)
#define GROUPS (W2_ / 2)              // 128 two-column groups per output row
#define NTHREADS 512

__global__ __launch_bounds__(NTHREADS)
void haar_kernel(const float* __restrict__ x, float* __restrict__ out) {
    // total items = B*C*H2*GROUPS = 16,777,216 < 2^31 -> 32-bit index math
    unsigned idx = blockIdx.x * (unsigned)NTHREADS + threadIdx.x;
    unsigned g  = idx & (GROUPS - 1);        // % 128
    unsigned t  = idx >> 7;
    unsigned h2 = t & (H2_ - 1);             // % 256
    t >>= 8;
    unsigned c  = t & (C_ - 1);              // % 64
    unsigned b  = t >> 6;

    const unsigned in_plane = (b * C_ + c) * (H_ * W_);          // < 2^27
    const unsigned in_row0  = in_plane + (2u * h2) * W_ + 4u * g;
    const unsigned in_row1  = in_row0 + W_;

    float4 r0 = *reinterpret_cast<const float4*>(x + in_row0);
    float4 r1 = *reinterpret_cast<const float4*>(x + in_row1);

    // Column j=0: pair (r.x, r.y); column j=1: pair (r.z, r.w)
    float s0x = r0.x + r0.y,  s0z = r0.z + r0.w;   // row0 sums
    float s1x = r1.x + r1.y,  s1z = r1.z + r1.w;   // row1 sums
    float d0x = r0.y - r0.x,  d0z = r0.w - r0.z;   // row0 diffs
    float d1x = r1.y - r1.x,  d1z = r1.w - r1.z;   // row1 diffs

    float2 ll = make_float2(0.5f * (s0x + s1x), 0.5f * (s0z + s1z));
    float2 lh = make_float2(0.5f * (s1x - s0x), 0.5f * (s1z - s0z));
    float2 hl = make_float2(0.5f * (d0x + d1x), 0.5f * (d0z + d1z));
    float2 hh = make_float2(0.5f * (d1x - d0x), 0.5f * (d1z - d0z));

    const unsigned out_base =
        ((b * (4 * C_) + 4 * c) * H2_ + h2) * W2_ + 2u * g;
    const unsigned ps = H2_ * W2_;   // plane stride = 65536

    *reinterpret_cast<float2*>(out + out_base)          = ll;
    *reinterpret_cast<float2*>(out + out_base + ps)     = lh;
    *reinterpret_cast<float2*>(out + out_base + 2 * ps) = hl;
    *reinterpret_cast<float2*>(out + out_base + 3 * ps) = hh;
}

extern "C" void kernel_launch(void* const* d_in, const int* in_sizes, int n_in,
                              void* d_out, int out_size) {
    const float* x = (const float*)d_in[0];
    float* out = (float*)d_out;
    const unsigned total_threads = (unsigned)B_ * C_ * H2_ * GROUPS; // 16,777,216
    const int blocks = (int)(total_threads / NTHREADS);               // 32768
    haar_kernel<<<blocks, NTHREADS>>>(x, out);
}

// round 16
// speedup vs baseline: 1.0025x; 1.0025x over previous
#include <cuda_runtime.h>
#include <cuda_bf16.h>

// Haar wavelet 2x2 transform — FINAL champion (512-thread CTAs).
// Input:  x[B=8, C=64, H=512, W=512] fp32
// Output: out[B=8, 4*C=256, H/2=256, W/2=256] fp32
// out channel = 4*c + band, band in {ll, lh, hl, hh}.
//
// One thread = 2 output columns (1 float2 per plane):
//   loads  : LDG.128 lane-dense (512 B contiguous per warp per instruction)
//   stores : STG.64 lane-dense (256 B contiguous per warp per instruction)
// Every memory instruction touches each 128B line exactly once.
// 15-round sweep (MLP, lane density, cache policy, persistence, CTA size)
// converged all well-formed variants to ~6.8 TB/s (85-87% of 8 TB/s spec) —
// the 1:1 read/write mixed-stream HBM ceiling. Traffic is minimal (1 GiB).

#define B_ 8
#define C_ 64
#define H_ 512
#define W_ 512
#define H2_ (H_ / 2)
#define W2_ (W_ / 2)
#define GROUPS (W2_ / 2)              // 128 two-column groups per output row
#define NTHREADS 512

__global__ __launch_bounds__(NTHREADS)
void haar_kernel(const float* __restrict__ x, float* __restrict__ out) {
    // total items = B*C*H2*GROUPS = 16,777,216 < 2^31 -> 32-bit index math
    unsigned idx = blockIdx.x * (unsigned)NTHREADS + threadIdx.x;
    unsigned g  = idx & (GROUPS - 1);        // % 128
    unsigned t  = idx >> 7;
    unsigned h2 = t & (H2_ - 1);             // % 256
    t >>= 8;
    unsigned c  = t & (C_ - 1);              // % 64
    unsigned b  = t >> 6;

    const unsigned in_plane = (b * C_ + c) * (H_ * W_);          // < 2^27
    const unsigned in_row0  = in_plane + (2u * h2) * W_ + 4u * g;
    const unsigned in_row1  = in_row0 + W_;

    float4 r0 = *reinterpret_cast<const float4*>(x + in_row0);
    float4 r1 = *reinterpret_cast<const float4*>(x + in_row1);

    // Column j=0: pair (r.x, r.y); column j=1: pair (r.z, r.w)
    float s0x = r0.x + r0.y,  s0z = r0.z + r0.w;   // row0 sums
    float s1x = r1.x + r1.y,  s1z = r1.z + r1.w;   // row1 sums
    float d0x = r0.y - r0.x,  d0z = r0.w - r0.z;   // row0 diffs
    float d1x = r1.y - r1.x,  d1z = r1.w - r1.z;   // row1 diffs

    float2 ll = make_float2(0.5f * (s0x + s1x), 0.5f * (s0z + s1z));
    float2 lh = make_float2(0.5f * (s1x - s0x), 0.5f * (s1z - s0z));
    float2 hl = make_float2(0.5f * (d0x + d1x), 0.5f * (d0z + d1z));
    float2 hh = make_float2(0.5f * (d1x - d0x), 0.5f * (d1z - d0z));

    const unsigned out_base =
        ((b * (4 * C_) + 4 * c) * H2_ + h2) * W2_ + 2u * g;
    const unsigned ps = H2_ * W2_;   // plane stride = 65536

    *reinterpret_cast<float2*>(out + out_base)          = ll;
    *reinterpret_cast<float2*>(out + out_base + ps)     = lh;
    *reinterpret_cast<float2*>(out + out_base + 2 * ps) = hl;
    *reinterpret_cast<float2*>(out + out_base + 3 * ps) = hh;
}

extern "C" void kernel_launch(void* const* d_in, const int* in_sizes, int n_in,
                              void* d_out, int out_size) {
    const float* x = (const float*)d_in[0];
    float* out = (float*)d_out;
    const unsigned total_threads = (unsigned)B_ * C_ * H2_ * GROUPS; // 16,777,216
    const int blocks = (int)(total_threads / NTHREADS);               // 32768
    haar_kernel<<<blocks, NTHREADS>>>(x, out);
}